// round 4
// baseline (speedup 1.0000x reference)
#include <cuda_runtime.h>

// out[b,j,h] = (1/N) * sum_i sum_g W[b,i,j,h,g] * x[b,i,g]
// B=16, N=32, H=64. W: 256 MiB fp32 streamed once -> pure HBM-bound.
//
// R4: split each (b,j) across the h dimension -> 1024 CTAs x 256KB.
// h-split means disjoint outputs: no atomics, no init kernel, deterministic.
// Finer work grains + dynamic block dispatch fix the 3-vs-4 CTA/SM imbalance
// that capped R1 at DRAM=82% (3.46/4 = 86.5% static-residency ceiling).
// Body kept light (2 loads/i/thread, unroll 2) for high residency.

#define BB 16
#define NN 32
#define HH 64

__global__ __launch_bounds__(256)
void msg_nn_kernel(const float4* __restrict__ W,
                   const float4* __restrict__ X,
                   float* __restrict__ out)
{
    const int blk = blockIdx.x;       // 0..1023
    const int bj  = blk >> 1;         // 0..511
    const int hh  = blk & 1;          // h-half: 0 -> h in [0,32), 1 -> [32,64)
    const int b   = bj >> 5;
    const int j   = bj & (NN - 1);

    __shared__ float4 xs[NN * HH / 4];   // x[b,:,:] = 512 float4 = 8 KB

    const int t = threadIdx.x;           // 0..255

    const float4* xb = X + (size_t)b * (NN * HH / 4);
    xs[t]       = xb[t];
    xs[t + 256] = xb[t + 256];
    __syncthreads();

    const int g4 = t & 15;               // g-quad
    const int h0 = t >> 4;               // 0..15 within the half

    // W[b, i, j, hh*32 + h, g]: per i an 8KB chunk (512 float4)
    const size_t tileF4 = (size_t)HH * HH / 4;        // 1024
    const size_t IS     = (size_t)NN * tileF4;        // 32768 f4 (i stride)
    const float4* Wbase = W + ((size_t)b * NN * NN + j) * tileF4
                            + (size_t)hh * 512;

    float acc0 = 0.f, acc1 = 0.f;

    #pragma unroll 2
    for (int i = 0; i < NN; ++i) {
        const float4* tp = Wbase + (size_t)i * IS;
        const float4 w0 = __ldcs(tp + t);          // h = h0
        const float4 w1 = __ldcs(tp + t + 256);    // h = h0 + 16
        const float4 xv = xs[i * 16 + g4];

        acc0 += w0.x * xv.x + w0.y * xv.y + w0.z * xv.z + w0.w * xv.w;
        acc1 += w1.x * xv.x + w1.y * xv.y + w1.z * xv.z + w1.w * xv.w;
    }

    // Reduce 16 g-quads per h within each contiguous 16-lane group.
    const unsigned mask = 0xFFFFFFFFu;
    #pragma unroll
    for (int off = 8; off > 0; off >>= 1) {
        acc0 += __shfl_down_sync(mask, acc0, off);
        acc1 += __shfl_down_sync(mask, acc1, off);
    }

    if (g4 == 0) {
        const float sc = 1.0f / (float)NN;
        float* o = out + (size_t)bj * HH + hh * 32 + h0;
        o[0]  = acc0 * sc;
        o[16] = acc1 * sc;
    }
}

extern "C" void kernel_launch(void* const* d_in, const int* in_sizes, int n_in,
                              void* d_out, int out_size)
{
    const float4* W = (const float4*)d_in[0];   // edge_wgt [B,N,N,H,H] fp32
    const float4* X = (const float4*)d_in[1];   // node_hidden [B,N,H] fp32
    float* out = (float*)d_out;                 // [B,N,H] fp32

    msg_nn_kernel<<<BB * NN * 2, 256>>>(W, X, out);   // 1024 CTAs
}

// round 5
// speedup vs baseline: 1.1008x; 1.1008x over previous
#include <cuda_runtime.h>

// out[b,j,h] = (1/N) * sum_i sum_g W[b,i,j,h,g] * x[b,i,g]
// B=16, N=32, H=64. W: 256 MiB fp32 streamed once -> pure HBM-bound.
//
// R5 = R4's h-split balance (1024 CTAs x 128KB, disjoint outputs, no atomics)
//    + R1's exact body shape (4 LDG.128/thread/iter by fusing two i's per
//      iteration, #pragma unroll 2, no __ldcs, launch_bounds(256,4)).
// R1 capped at DRAM=82% ~= 86.5% static-residency ceiling (68 SMs w/ 4 CTAs,
// 80 w/ 3). Finer grains + work-steal should lift that; R4 proved grain-size
// alone is fine but only if per-warp load batching stays at R1 level.

#define BB 16
#define NN 32
#define HH 64

__global__ __launch_bounds__(256, 4)
void msg_nn_kernel(const float4* __restrict__ W,
                   const float4* __restrict__ X,
                   float* __restrict__ out)
{
    const int blk = blockIdx.x;       // 0..1023
    const int bj  = blk >> 1;         // 0..511
    const int hh  = blk & 1;          // h-half: 0 -> h in [0,32), 1 -> [32,64)
    const int b   = bj >> 5;
    const int j   = bj & (NN - 1);

    __shared__ float4 xs[NN * HH / 4];   // x[b,:,:] = 512 float4 = 8 KB

    const int t = threadIdx.x;           // 0..255

    const float4* xb = X + (size_t)b * (NN * HH / 4);
    xs[t]       = xb[t];
    xs[t + 256] = xb[t + 256];
    __syncthreads();

    const int g4 = t & 15;               // g-quad
    const int h0 = t >> 4;               // 0..15 within the half

    // Per i, this CTA's half-tile W[b,i,j,hh*32:(hh+1)*32,:] = 512 float4 (8KB).
    const size_t tileF4 = (size_t)HH * HH / 4;        // 1024
    const size_t IS     = (size_t)NN * tileF4;        // 32768 f4 (i stride)
    const float4* Wbase = W + ((size_t)b * NN * NN + j) * tileF4
                            + (size_t)hh * 512;

    float acc0 = 0.f, acc1 = 0.f;

    // Two i's per iteration -> 4 independent LDG.128 per thread per iter
    // (same load-batching shape as R1's 4-load body).
    #pragma unroll 2
    for (int i = 0; i < NN; i += 2) {
        const float4* tpA = Wbase + (size_t)i * IS;
        const float4* tpB = tpA + IS;

        const float4 a0 = tpA[t];          // i,   h = h0
        const float4 a1 = tpA[t + 256];    // i,   h = h0+16
        const float4 b0 = tpB[t];          // i+1, h = h0
        const float4 b1 = tpB[t + 256];    // i+1, h = h0+16

        const float4 xA = xs[i * 16 + g4];
        const float4 xB = xs[i * 16 + 16 + g4];

        acc0 += a0.x * xA.x + a0.y * xA.y + a0.z * xA.z + a0.w * xA.w;
        acc1 += a1.x * xA.x + a1.y * xA.y + a1.z * xA.z + a1.w * xA.w;
        acc0 += b0.x * xB.x + b0.y * xB.y + b0.z * xB.z + b0.w * xB.w;
        acc1 += b1.x * xB.x + b1.y * xB.y + b1.z * xB.z + b1.w * xB.w;
    }

    // Reduce 16 g-quads per h within each contiguous 16-lane group.
    const unsigned mask = 0xFFFFFFFFu;
    #pragma unroll
    for (int off = 8; off > 0; off >>= 1) {
        acc0 += __shfl_down_sync(mask, acc0, off);
        acc1 += __shfl_down_sync(mask, acc1, off);
    }

    if (g4 == 0) {
        const float sc = 1.0f / (float)NN;
        float* o = out + (size_t)bj * HH + hh * 32 + h0;
        o[0]  = acc0 * sc;
        o[16] = acc1 * sc;
    }
}

extern "C" void kernel_launch(void* const* d_in, const int* in_sizes, int n_in,
                              void* d_out, int out_size)
{
    const float4* W = (const float4*)d_in[0];   // edge_wgt [B,N,N,H,H] fp32
    const float4* X = (const float4*)d_in[1];   // node_hidden [B,N,H] fp32
    float* out = (float*)d_out;                 // [B,N,H] fp32

    msg_nn_kernel<<<BB * NN * 2, 256>>>(W, X, out);   // 1024 CTAs
}